// round 12
// baseline (speedup 1.0000x reference)
#include <cuda_runtime.h>
#include <cuda_bf16.h>
#include <math.h>
#include <stdint.h>

// Problem constants
#define BB 32
#define NN 2048
#define DD 512
#define KK 256
#define NEG_SLOPE 0.01f

// Scratch (__device__ globals; no allocation allowed)
__device__ float g_vQp[BB * KK];                 // vQ @ Wq + bq
__device__ float g_t[BB * DD];                   // sum_n exp(s_n) * vI[n,:]
__device__ float g_Z[BB];                        // sum_n exp(s_n)
__device__ __nv_bfloat16 g_WiTbf[KK * DD];       // Wi^T [k][d] in bf16

// ---------------------------------------------------------------------------
// Helpers
// ---------------------------------------------------------------------------
__device__ __forceinline__ uint32_t smem_u32(const void* p) {
    uint32_t a;
    asm("{ .reg .u64 t; cvta.to.shared.u64 t, %1; cvt.u32.u64 %0, t; }"
        : "=r"(a) : "l"(p));
    return a;
}
__device__ __forceinline__ uint32_t pack_bf16(float lo, float hi) {
    uint32_t r;
    asm("cvt.rn.bf16x2.f32 %0, %1, %2;" : "=r"(r) : "f"(hi), "f"(lo));
    return r;
}
__device__ __forceinline__ void cp16(uint32_t smem_addr, const void* gptr) {
    asm volatile("cp.async.cg.shared.global [%0], [%1], 16;"
                 :: "r"(smem_addr), "l"(gptr) : "memory");
}
#define CP_COMMIT() asm volatile("cp.async.commit_group;" ::: "memory")
#define CP_WAIT(n)  asm volatile("cp.async.wait_group %0;" :: "n"(n) : "memory")

__device__ __forceinline__ void ldsm4(uint32_t& r0, uint32_t& r1,
                                      uint32_t& r2, uint32_t& r3, uint32_t addr) {
    asm volatile("ldmatrix.sync.aligned.m8n8.x4.shared.b16 {%0,%1,%2,%3}, [%4];"
                 : "=r"(r0), "=r"(r1), "=r"(r2), "=r"(r3) : "r"(addr));
}
// m16n8k16 bf16 MMA (base-target PTX, sm_80+)
__device__ __forceinline__ void mma_bf16(float* d,
                                         uint32_t a0, uint32_t a1,
                                         uint32_t a2, uint32_t a3,
                                         uint32_t b0, uint32_t b1) {
    asm volatile(
        "mma.sync.aligned.m16n8k16.row.col.f32.bf16.bf16.f32 "
        "{%0,%1,%2,%3}, {%4,%5,%6,%7}, {%8,%9}, {%0,%1,%2,%3};"
        : "+f"(d[0]), "+f"(d[1]), "+f"(d[2]), "+f"(d[3])
        : "r"(a0), "r"(a1), "r"(a2), "r"(a3), "r"(b0), "r"(b1));
}

// ---------------------------------------------------------------------------
// Kernel 1 (fused prep): blocks 0..127 transpose Wi -> WiTbf (bf16);
// blocks 128..159 compute vQp[b] = vQ[b] @ Wq + bq (float4-row matvec)
// and zero g_t[b], g_Z[b]. 1024 threads/block.
// ---------------------------------------------------------------------------
__global__ __launch_bounds__(1024)
void prep_kernel(const float* __restrict__ Wi,
                 const float* __restrict__ vQ,
                 const float* __restrict__ Wq,
                 const float* __restrict__ bq) {
    __shared__ union {
        float tr[32][33];
        struct { float sq[DD]; float4 sred[8][64]; } v;
    } sm;

    const int bid = blockIdx.x;
    const int tid = threadIdx.x;

    if (bid < 128) {
        // ---- transpose: Wi[d][k] -> WiTbf[k][d] ----
        const int d0 = (bid >> 3) * 32, k0 = (bid & 7) * 32;
        const int tx = tid & 31, ty = tid >> 5;
        sm.tr[ty][tx] = Wi[(d0 + ty) * KK + (k0 + tx)];
        __syncthreads();
        g_WiTbf[(size_t)(k0 + ty) * DD + d0 + tx] =
            __float2bfloat16_rn(sm.tr[tx][ty]);
    } else {
        // ---- vQp for batch b ----
        const int b = bid - 128;
        if (tid < DD) sm.v.sq[tid] = vQ[b * DD + tid];
        if (tid < DD) g_t[b * DD + tid] = 0.0f;
        if (tid == 0) g_Z[b] = 0.0f;
        __syncthreads();

        if (tid < 512) {
            const int kq = tid & 63;     // k = kq*4
            const int dg = tid >> 6;     // 0..7 -> d range [dg*64, +64)
            const float4* w = (const float4*)Wq + kq;
            float4 acc = make_float4(0.0f, 0.0f, 0.0f, 0.0f);
            const int d0 = dg * 64;
#pragma unroll 8
            for (int d = d0; d < d0 + 64; d++) {
                const float4 wv = w[(size_t)d * (KK / 4)];
                const float s = sm.v.sq[d];
                acc.x = fmaf(s, wv.x, acc.x);
                acc.y = fmaf(s, wv.y, acc.y);
                acc.z = fmaf(s, wv.z, acc.z);
                acc.w = fmaf(s, wv.w, acc.w);
            }
            sm.v.sred[dg][kq] = acc;
        }
        __syncthreads();
        if (tid < 64) {
            float4 a = sm.v.sred[0][tid];
#pragma unroll
            for (int g = 1; g < 8; g++) {
                const float4 p = sm.v.sred[g][tid];
                a.x += p.x; a.y += p.y; a.z += p.z; a.w += p.w;
            }
            const float4 bqv = ((const float4*)bq)[tid];
            a.x += bqv.x; a.y += bqv.y; a.z += bqv.z; a.w += bqv.w;
            ((float4*)(g_vQp + b * KK))[tid] = a;
        }
    }
}

// ---------------------------------------------------------------------------
// Kernel 2 (dominant, fully fused): scores GEMM (bf16 mma.sync, 4x4 warp map,
// KC=64) -> unnormalized exp -> Z partial + t partial in one CTA pass.
// Warp w: row strip (w&3)*32, col quarter (w>>2)*64.
// Smem rows 72 bf16 (144 B): 9r mod 8 = r mod 8 -> ldsm conflict-free.
// ---------------------------------------------------------------------------
#define M_TILE 128
#define KC 64
#define NCH (DD / KC)               // 8
#define AROW 144                    // bytes per smem row (64 bf16 + 8 pad)
#define A_BYTES (M_TILE * AROW)     // 18432
#define B_BYTES (KK * AROW)         // 36864
#define STG_BYTES (A_BYTES + B_BYTES)   // 55296
#define SCORES_SMEM (2 * STG_BYTES)     // 110592

__global__ __launch_bounds__(512, 1)
void scores_mma_kernel(const float* __restrict__ vI,
                       const float* __restrict__ Wp) {
    extern __shared__ char smem[];
    __shared__ float svqp[KK];
    __shared__ float swp[KK];
    __shared__ float sred[4][M_TILE];
    __shared__ float sw[M_TILE];

    const int tid  = threadIdx.x;
    const int lane = tid & 31;
    const int wid  = tid >> 5;
    const int b    = blockIdx.y;
    const int n0   = blockIdx.x * M_TILE;

    if (tid < KK) {
        svqp[tid] = g_vQp[b * KK + tid];
        swp[tid]  = Wp[tid];
    }

    const uint32_t sb = smem_u32(smem);

    // ---- A producer: 2048 float4-quads/chunk, 4 per thread ----
    const float* srcA[4];
    uint32_t offA[4];
#pragma unroll
    for (int i = 0; i < 4; i++) {
        const int qi = tid + 512 * i;
        const int row = qi >> 4, seg = qi & 15;
        srcA[i] = vI + ((size_t)b * NN + n0 + row) * DD + seg * 4;
        offA[i] = row * AROW + seg * 8;
    }
    // ---- B producer: 2048 16B-quads/chunk, 4 per thread ----
    const __nv_bfloat16* srcB[4];
    uint32_t dstB[4];
#pragma unroll
    for (int i = 0; i < 4; i++) {
        const int qi = tid + 512 * i;
        const int row = qi >> 3, kq = qi & 7;
        srcB[i] = g_WiTbf + (size_t)row * DD + kq * 8;
        dstB[i] = sb + A_BYTES + row * AROW + kq * 16;
    }

    // ---- fragment base addresses (warp: strip s rows, quarter q cols) ----
    const int s = wid & 3;            // 0..3 -> rows s*32..+31
    const int q = wid >> 2;           // 0..3 -> cols q*64..+63
    const uint32_t addrA_base =
        sb + (s * 32 + (lane & 15)) * AROW + ((lane >> 4) & 1) * 16;
    const uint32_t addrB_base =
        sb + A_BYTES +
        (q * 64 + (lane & 7) + ((lane >> 4) & 1) * 8) * AROW +
        ((lane >> 3) & 1) * 16;

    float acc[16][4];
#pragma unroll
    for (int j = 0; j < 16; j++)
#pragma unroll
        for (int e = 0; e < 4; e++) acc[j][e] = 0.0f;

    // ---- prologue: fill stage 0 ----
#pragma unroll
    for (int i = 0; i < 4; i++) {
        float4 v = *(const float4*)srcA[i];
        uint2 p = make_uint2(pack_bf16(v.x, v.y), pack_bf16(v.z, v.w));
        *(uint2*)(smem + offA[i]) = p;
        cp16(dstB[i], srcB[i]);
    }
    CP_COMMIT();
    CP_WAIT(0);
    __syncthreads();

    for (int c = 0; c < NCH; c++) {
        const int st = c & 1;
        const uint32_t so = st * STG_BYTES;
        const uint32_t so_n = (st ^ 1) * STG_BYTES;

        float4 pa[4];
        const bool pf = (c + 1 < NCH);
        if (pf) {
            const int d0 = (c + 1) * KC;
#pragma unroll
            for (int i = 0; i < 4; i++) {
                pa[i] = *(const float4*)(srcA[i] + d0);
                cp16(dstB[i] + so_n, srcB[i] + d0);
            }
            CP_COMMIT();
        }

        // ---- MMA on stage st: 4 ksteps x (2 A-ldsm + 4 B-ldsm + 16 MMA) ----
#pragma unroll
        for (int ks = 0; ks < 4; ks++) {
            uint32_t a[2][4];
#pragma unroll
            for (int mt = 0; mt < 2; mt++)
                ldsm4(a[mt][0], a[mt][1], a[mt][2], a[mt][3],
                      addrA_base + so + mt * 16 * AROW + ks * 32);
#pragma unroll
            for (int pt = 0; pt < 4; pt++) {
                uint32_t b0, b1, b2, b3;
                ldsm4(b0, b1, b2, b3,
                      addrB_base + so + pt * 16 * AROW + ks * 32);
#pragma unroll
                for (int mt = 0; mt < 2; mt++) {
                    mma_bf16(acc[mt * 8 + pt * 2],
                             a[mt][0], a[mt][1], a[mt][2], a[mt][3], b0, b1);
                    mma_bf16(acc[mt * 8 + pt * 2 + 1],
                             a[mt][0], a[mt][1], a[mt][2], a[mt][3], b2, b3);
                }
            }
        }

        if (pf) {
#pragma unroll
            for (int i = 0; i < 4; i++) {
                uint2 p = make_uint2(pack_bf16(pa[i].x, pa[i].y),
                                     pack_bf16(pa[i].z, pa[i].w));
                *(uint2*)(smem + so_n + offA[i]) = p;
            }
            CP_WAIT(0);
        }
        __syncthreads();
    }

    // ---- epilogue 1: +vQp, leaky-relu, dot(Wp); per-quarter row partials ----
    float p00 = 0.0f, p01 = 0.0f, p10 = 0.0f, p11 = 0.0f;
#pragma unroll
    for (int mt = 0; mt < 2; mt++) {
#pragma unroll
        for (int j2 = 0; j2 < 8; j2++) {
            const int cb = q * 64 + j2 * 8 + 2 * (lane & 3);
            const float* ac = acc[mt * 8 + j2];
#pragma unroll
            for (int e = 0; e < 2; e++) {
                const float vq = svqp[cb + e];
                const float wp = swp[cb + e];
                float x = ac[e] + vq;
                float h = x > 0.0f ? x : NEG_SLOPE * x;
                float x2 = ac[2 + e] + vq;
                float h2 = x2 > 0.0f ? x2 : NEG_SLOPE * x2;
                if (mt == 0) { p00 = fmaf(h, wp, p00); p01 = fmaf(h2, wp, p01); }
                else         { p10 = fmaf(h, wp, p10); p11 = fmaf(h2, wp, p11); }
            }
        }
    }
    p00 += __shfl_xor_sync(0xffffffffu, p00, 1);
    p00 += __shfl_xor_sync(0xffffffffu, p00, 2);
    p01 += __shfl_xor_sync(0xffffffffu, p01, 1);
    p01 += __shfl_xor_sync(0xffffffffu, p01, 2);
    p10 += __shfl_xor_sync(0xffffffffu, p10, 1);
    p10 += __shfl_xor_sync(0xffffffffu, p10, 2);
    p11 += __shfl_xor_sync(0xffffffffu, p11, 1);
    p11 += __shfl_xor_sync(0xffffffffu, p11, 2);
    if ((lane & 3) == 0) {
        const int r = s * 32 + (lane >> 2);
        sred[q][r]      = p00;
        sred[q][r + 8]  = p01;
        sred[q][r + 16] = p10;
        sred[q][r + 24] = p11;
    }
    __syncthreads();

    // ---- epilogue 2: w = exp(score); Z partial ----
    if (tid < M_TILE)
        sw[tid] = __expf((sred[0][tid] + sred[1][tid]) +
                         (sred[2][tid] + sred[3][tid]));
    __syncthreads();
    if (tid < 32) {
        float z = (sw[tid] + sw[tid + 32]) + (sw[tid + 64] + sw[tid + 96]);
        z += __shfl_xor_sync(0xffffffffu, z, 16);
        z += __shfl_xor_sync(0xffffffffu, z, 8);
        z += __shfl_xor_sync(0xffffffffu, z, 4);
        z += __shfl_xor_sync(0xffffffffu, z, 2);
        z += __shfl_xor_sync(0xffffffffu, z, 1);
        if (tid == 0) atomicAdd(&g_Z[b], z);
    }

    // ---- epilogue 3: t[b,d] += sum_n w_n * vI[n0+n, d] (L2-hot fp32 re-read)
    {
        const float* vb = vI + ((size_t)b * NN + n0) * DD + tid;  // d = tid
        float a0 = 0.0f, a1 = 0.0f, a2 = 0.0f, a3 = 0.0f;
#pragma unroll 8
        for (int n = 0; n < M_TILE; n += 4) {
            a0 = fmaf(sw[n],     vb[(size_t)n * DD],       a0);
            a1 = fmaf(sw[n + 1], vb[(size_t)(n + 1) * DD], a1);
            a2 = fmaf(sw[n + 2], vb[(size_t)(n + 2) * DD], a2);
            a3 = fmaf(sw[n + 3], vb[(size_t)(n + 3) * DD], a3);
        }
        atomicAdd(&g_t[b * DD + tid], (a0 + a1) + (a2 + a3));
    }
}

// ---------------------------------------------------------------------------
// Kernel 3: out[b,k] = (t[b,:]/Z[b]) @ Wi[:,k] + vQp[b,k]
// float4-row matvec: thread = (k-quad, d-group of 64); one coalesced LDG.128
// per step feeding 4 independent FMA chains. grid = B, block = 512.
// ---------------------------------------------------------------------------
__global__ __launch_bounds__(512)
void out_kernel(const float* __restrict__ Wi, float* __restrict__ out) {
    const int b   = blockIdx.x;
    const int tid = threadIdx.x;
    const int kq  = tid & 63;    // k = kq*4
    const int dg  = tid >> 6;    // 0..7 -> d range [dg*64, +64)

    __shared__ float st[DD];
    __shared__ float4 sred[8][64];

    const float invZ = 1.0f / g_Z[b];
    st[tid] = g_t[b * DD + tid] * invZ;
    __syncthreads();

    const float4* w = (const float4*)Wi + kq;
    float4 acc = make_float4(0.0f, 0.0f, 0.0f, 0.0f);
    const int d0 = dg * 64;
#pragma unroll 8
    for (int d = d0; d < d0 + 64; d++) {
        const float4 wv = w[(size_t)d * (KK / 4)];
        const float s = st[d];
        acc.x = fmaf(s, wv.x, acc.x);
        acc.y = fmaf(s, wv.y, acc.y);
        acc.z = fmaf(s, wv.z, acc.z);
        acc.w = fmaf(s, wv.w, acc.w);
    }
    sred[dg][kq] = acc;
    __syncthreads();

    if (tid < 64) {
        float4 a = sred[0][tid];
#pragma unroll
        for (int g = 1; g < 8; g++) {
            const float4 p = sred[g][tid];
            a.x += p.x; a.y += p.y; a.z += p.z; a.w += p.w;
        }
        const float4 vq = ((const float4*)(g_vQp + b * KK))[tid];
        a.x += vq.x; a.y += vq.y; a.z += vq.z; a.w += vq.w;
        ((float4*)(out + b * KK))[tid] = a;
    }
}

// ---------------------------------------------------------------------------
// Launch. Inputs: vI, vQ, Wi, Wq, bq, Wp, bp
// ---------------------------------------------------------------------------
extern "C" void kernel_launch(void* const* d_in, const int* in_sizes, int n_in,
                              void* d_out, int out_size) {
    const float* vI = (const float*)d_in[0];
    const float* vQ = (const float*)d_in[1];
    const float* Wi = (const float*)d_in[2];
    const float* Wq = (const float*)d_in[3];
    const float* bq = (const float*)d_in[4];
    const float* Wp = (const float*)d_in[5];
    // bp shifts scores uniformly -> softmax-invariant; unused.
    float* out = (float*)d_out;

    cudaFuncSetAttribute(scores_mma_kernel,
                         cudaFuncAttributeMaxDynamicSharedMemorySize, SCORES_SMEM);

    prep_kernel<<<128 + BB, 1024>>>(Wi, vQ, Wq, bq);
    {
        dim3 grid(NN / M_TILE, BB);  // 16 x 32 = 512 CTAs
        scores_mma_kernel<<<grid, 512, SCORES_SMEM>>>(vI, Wp);
    }
    out_kernel<<<BB, 512>>>(Wi, out);
}

// round 15
// speedup vs baseline: 1.1359x; 1.1359x over previous
#include <cuda_runtime.h>
#include <cuda_bf16.h>
#include <math.h>
#include <stdint.h>

// Problem constants
#define BB 32
#define NN 2048
#define DD 512
#define KK 256
#define NEG_SLOPE 0.01f

// Scratch (__device__ globals; no allocation allowed)
__device__ float g_vQp[BB * KK];                 // vQ @ Wq + bq
__device__ float g_t[BB * DD];                   // sum_n exp(s_n) * vI[n,:]
__device__ float g_Z[BB];                        // sum_n exp(s_n)
__device__ __nv_bfloat16 g_WiTbf[KK * DD];       // Wi^T [k][d] in bf16

// ---------------------------------------------------------------------------
// Helpers
// ---------------------------------------------------------------------------
__device__ __forceinline__ uint32_t smem_u32(const void* p) {
    uint32_t a;
    asm("{ .reg .u64 t; cvta.to.shared.u64 t, %1; cvt.u32.u64 %0, t; }"
        : "=r"(a) : "l"(p));
    return a;
}
__device__ __forceinline__ uint32_t pack_bf16(float lo, float hi) {
    uint32_t r;
    asm("cvt.rn.bf16x2.f32 %0, %1, %2;" : "=r"(r) : "f"(hi), "f"(lo));
    return r;
}
__device__ __forceinline__ void cp16(uint32_t smem_addr, const void* gptr) {
    asm volatile("cp.async.cg.shared.global [%0], [%1], 16;"
                 :: "r"(smem_addr), "l"(gptr) : "memory");
}
#define CP_COMMIT() asm volatile("cp.async.commit_group;" ::: "memory")
#define CP_WAIT(n)  asm volatile("cp.async.wait_group %0;" :: "n"(n) : "memory")

__device__ __forceinline__ void ldsm4(uint32_t& r0, uint32_t& r1,
                                      uint32_t& r2, uint32_t& r3, uint32_t addr) {
    asm volatile("ldmatrix.sync.aligned.m8n8.x4.shared.b16 {%0,%1,%2,%3}, [%4];"
                 : "=r"(r0), "=r"(r1), "=r"(r2), "=r"(r3) : "r"(addr));
}
// m16n8k16 bf16 MMA (base-target PTX, sm_80+)
__device__ __forceinline__ void mma_bf16(float* d,
                                         uint32_t a0, uint32_t a1,
                                         uint32_t a2, uint32_t a3,
                                         uint32_t b0, uint32_t b1) {
    asm volatile(
        "mma.sync.aligned.m16n8k16.row.col.f32.bf16.bf16.f32 "
        "{%0,%1,%2,%3}, {%4,%5,%6,%7}, {%8,%9}, {%0,%1,%2,%3};"
        : "+f"(d[0]), "+f"(d[1]), "+f"(d[2]), "+f"(d[3])
        : "r"(a0), "r"(a1), "r"(a2), "r"(a3), "r"(b0), "r"(b1));
}

// ---------------------------------------------------------------------------
// Kernel 0b: WiTbf[k][d] = bf16(Wi[d][k])
// ---------------------------------------------------------------------------
__global__ void transpose_wi_kernel(const float* __restrict__ Wi) {
    __shared__ float t[32][33];
    int d0 = blockIdx.x * 32, k0 = blockIdx.y * 32;
    t[threadIdx.y][threadIdx.x] = Wi[(d0 + threadIdx.y) * KK + (k0 + threadIdx.x)];
    __syncthreads();
    g_WiTbf[(size_t)(k0 + threadIdx.y) * DD + d0 + threadIdx.x] =
        __float2bfloat16_rn(t[threadIdx.x][threadIdx.y]);
}

// ---------------------------------------------------------------------------
// Kernel 1: vQp = vQ @ Wq + bq  (split-d: grid (B,8), 32 k x 8 d-groups of 64)
// Also initializes out[b,k] = vQp (out_kernel atomically adds the attn part),
// and the blockIdx.y==0 slice zeroes g_t, g_Z for this replay.
// ---------------------------------------------------------------------------
__global__ __launch_bounds__(256)
void vqp_kernel(const float* __restrict__ vQ,
                const float* __restrict__ Wq,
                const float* __restrict__ bq,
                float* __restrict__ out) {
    const int b  = blockIdx.x;
    const int k0 = blockIdx.y * 32;
    const int tid = threadIdx.x;
    const int kl = tid & 31;
    const int dg = tid >> 5;

    __shared__ float sq[DD];
    __shared__ float sred[8][32];

    sq[tid]       = vQ[b * DD + tid];
    sq[tid + 256] = vQ[b * DD + 256 + tid];
    if (blockIdx.y == 0) {
        g_t[b * DD + tid] = 0.0f;
        g_t[b * DD + 256 + tid] = 0.0f;
        if (tid == 0) g_Z[b] = 0.0f;
    }
    __syncthreads();

    const float* w = Wq + k0 + kl;
    const int d0 = dg * 64;
    float a0 = 0.0f, a1 = 0.0f, a2 = 0.0f, a3 = 0.0f;
#pragma unroll 8
    for (int d = d0; d < d0 + 64; d += 4) {
        a0 = fmaf(sq[d],     w[(size_t)d * KK],       a0);
        a1 = fmaf(sq[d + 1], w[(size_t)(d + 1) * KK], a1);
        a2 = fmaf(sq[d + 2], w[(size_t)(d + 2) * KK], a2);
        a3 = fmaf(sq[d + 3], w[(size_t)(d + 3) * KK], a3);
    }
    sred[dg][kl] = (a0 + a1) + (a2 + a3);
    __syncthreads();
    if (tid < 32) {
        float s = 0.0f;
#pragma unroll
        for (int g = 0; g < 8; g++) s += sred[g][tid];
        const float v = bq[k0 + tid] + s;
        g_vQp[b * KK + k0 + tid] = v;
        out[b * KK + k0 + tid] = v;   // init; out_kernel atomically adds attn
    }
}

// ---------------------------------------------------------------------------
// Kernel 2 (dominant, fully fused): scores GEMM (bf16 mma.sync, 4x4 warp map,
// KC=64) -> unnormalized exp -> Z partial + t partial in one CTA pass.
// Warp w: row strip (w&3)*32, col quarter (w>>2)*64.
// Smem rows 72 bf16 (144 B): 9r mod 8 = r mod 8 -> ldsm conflict-free.
// ---------------------------------------------------------------------------
#define M_TILE 128
#define KC 64
#define NCH (DD / KC)               // 8
#define AROW 144                    // bytes per smem row (64 bf16 + 8 pad)
#define A_BYTES (M_TILE * AROW)     // 18432
#define B_BYTES (KK * AROW)         // 36864
#define STG_BYTES (A_BYTES + B_BYTES)   // 55296
#define SCORES_SMEM (2 * STG_BYTES)     // 110592

__global__ __launch_bounds__(512, 1)
void scores_mma_kernel(const float* __restrict__ vI,
                       const float* __restrict__ Wp) {
    extern __shared__ char smem[];
    __shared__ float svqp[KK];
    __shared__ float swp[KK];
    __shared__ float sred[4][M_TILE];
    __shared__ float sw[M_TILE];

    const int tid  = threadIdx.x;
    const int lane = tid & 31;
    const int wid  = tid >> 5;
    const int b    = blockIdx.y;
    const int n0   = blockIdx.x * M_TILE;

    if (tid < KK) {
        svqp[tid] = g_vQp[b * KK + tid];
        swp[tid]  = Wp[tid];
    }

    const uint32_t sb = smem_u32(smem);

    // ---- A producer: 2048 float4-quads/chunk, 4 per thread ----
    const float* srcA[4];
    uint32_t offA[4];
#pragma unroll
    for (int i = 0; i < 4; i++) {
        const int qi = tid + 512 * i;
        const int row = qi >> 4, seg = qi & 15;
        srcA[i] = vI + ((size_t)b * NN + n0 + row) * DD + seg * 4;
        offA[i] = row * AROW + seg * 8;
    }
    // ---- B producer: 2048 16B-quads/chunk, 4 per thread ----
    const __nv_bfloat16* srcB[4];
    uint32_t dstB[4];
#pragma unroll
    for (int i = 0; i < 4; i++) {
        const int qi = tid + 512 * i;
        const int row = qi >> 3, kq = qi & 7;
        srcB[i] = g_WiTbf + (size_t)row * DD + kq * 8;
        dstB[i] = sb + A_BYTES + row * AROW + kq * 16;
    }

    // ---- fragment base addresses (warp: strip s rows, quarter q cols) ----
    const int s = wid & 3;            // 0..3 -> rows s*32..+31
    const int q = wid >> 2;           // 0..3 -> cols q*64..+63
    const uint32_t addrA_base =
        sb + (s * 32 + (lane & 15)) * AROW + ((lane >> 4) & 1) * 16;
    const uint32_t addrB_base =
        sb + A_BYTES +
        (q * 64 + (lane & 7) + ((lane >> 4) & 1) * 8) * AROW +
        ((lane >> 3) & 1) * 16;

    float acc[16][4];
#pragma unroll
    for (int j = 0; j < 16; j++)
#pragma unroll
        for (int e = 0; e < 4; e++) acc[j][e] = 0.0f;

    // ---- prologue: fill stage 0 ----
#pragma unroll
    for (int i = 0; i < 4; i++) {
        float4 v = *(const float4*)srcA[i];
        uint2 p = make_uint2(pack_bf16(v.x, v.y), pack_bf16(v.z, v.w));
        *(uint2*)(smem + offA[i]) = p;
        cp16(dstB[i], srcB[i]);
    }
    CP_COMMIT();
    CP_WAIT(0);
    __syncthreads();

    for (int c = 0; c < NCH; c++) {
        const int st = c & 1;
        const uint32_t so = st * STG_BYTES;
        const uint32_t so_n = (st ^ 1) * STG_BYTES;

        float4 pa[4];
        const bool pf = (c + 1 < NCH);
        if (pf) {
            const int d0 = (c + 1) * KC;
#pragma unroll
            for (int i = 0; i < 4; i++) {
                pa[i] = *(const float4*)(srcA[i] + d0);
                cp16(dstB[i] + so_n, srcB[i] + d0);
            }
            CP_COMMIT();
        }

        // ---- MMA on stage st: 4 ksteps x (2 A-ldsm + 4 B-ldsm + 16 MMA) ----
#pragma unroll
        for (int ks = 0; ks < 4; ks++) {
            uint32_t a[2][4];
#pragma unroll
            for (int mt = 0; mt < 2; mt++)
                ldsm4(a[mt][0], a[mt][1], a[mt][2], a[mt][3],
                      addrA_base + so + mt * 16 * AROW + ks * 32);
#pragma unroll
            for (int pt = 0; pt < 4; pt++) {
                uint32_t b0, b1, b2, b3;
                ldsm4(b0, b1, b2, b3,
                      addrB_base + so + pt * 16 * AROW + ks * 32);
#pragma unroll
                for (int mt = 0; mt < 2; mt++) {
                    mma_bf16(acc[mt * 8 + pt * 2],
                             a[mt][0], a[mt][1], a[mt][2], a[mt][3], b0, b1);
                    mma_bf16(acc[mt * 8 + pt * 2 + 1],
                             a[mt][0], a[mt][1], a[mt][2], a[mt][3], b2, b3);
                }
            }
        }

        if (pf) {
#pragma unroll
            for (int i = 0; i < 4; i++) {
                uint2 p = make_uint2(pack_bf16(pa[i].x, pa[i].y),
                                     pack_bf16(pa[i].z, pa[i].w));
                *(uint2*)(smem + so_n + offA[i]) = p;
            }
            CP_WAIT(0);
        }
        __syncthreads();
    }

    // ---- epilogue 1: +vQp, leaky-relu, dot(Wp); per-quarter row partials ----
    float p00 = 0.0f, p01 = 0.0f, p10 = 0.0f, p11 = 0.0f;
#pragma unroll
    for (int mt = 0; mt < 2; mt++) {
#pragma unroll
        for (int j2 = 0; j2 < 8; j2++) {
            const int cb = q * 64 + j2 * 8 + 2 * (lane & 3);
            const float* ac = acc[mt * 8 + j2];
#pragma unroll
            for (int e = 0; e < 2; e++) {
                const float vq = svqp[cb + e];
                const float wp = swp[cb + e];
                float x = ac[e] + vq;
                float h = x > 0.0f ? x : NEG_SLOPE * x;
                float x2 = ac[2 + e] + vq;
                float h2 = x2 > 0.0f ? x2 : NEG_SLOPE * x2;
                if (mt == 0) { p00 = fmaf(h, wp, p00); p01 = fmaf(h2, wp, p01); }
                else         { p10 = fmaf(h, wp, p10); p11 = fmaf(h2, wp, p11); }
            }
        }
    }
    p00 += __shfl_xor_sync(0xffffffffu, p00, 1);
    p00 += __shfl_xor_sync(0xffffffffu, p00, 2);
    p01 += __shfl_xor_sync(0xffffffffu, p01, 1);
    p01 += __shfl_xor_sync(0xffffffffu, p01, 2);
    p10 += __shfl_xor_sync(0xffffffffu, p10, 1);
    p10 += __shfl_xor_sync(0xffffffffu, p10, 2);
    p11 += __shfl_xor_sync(0xffffffffu, p11, 1);
    p11 += __shfl_xor_sync(0xffffffffu, p11, 2);
    if ((lane & 3) == 0) {
        const int r = s * 32 + (lane >> 2);
        sred[q][r]      = p00;
        sred[q][r + 8]  = p01;
        sred[q][r + 16] = p10;
        sred[q][r + 24] = p11;
    }
    __syncthreads();

    // ---- epilogue 2: w = exp(score); Z partial ----
    if (tid < M_TILE)
        sw[tid] = __expf((sred[0][tid] + sred[1][tid]) +
                         (sred[2][tid] + sred[3][tid]));
    __syncthreads();
    if (tid < 32) {
        float z = (sw[tid] + sw[tid + 32]) + (sw[tid + 64] + sw[tid + 96]);
        z += __shfl_xor_sync(0xffffffffu, z, 16);
        z += __shfl_xor_sync(0xffffffffu, z, 8);
        z += __shfl_xor_sync(0xffffffffu, z, 4);
        z += __shfl_xor_sync(0xffffffffu, z, 2);
        z += __shfl_xor_sync(0xffffffffu, z, 1);
        if (tid == 0) atomicAdd(&g_Z[b], z);
    }

    // ---- epilogue 3: t[b,d] += sum_n w_n * vI[n0+n, d] (L2-hot fp32 re-read)
    {
        const float* vb = vI + ((size_t)b * NN + n0) * DD + tid;  // d = tid
        float a0 = 0.0f, a1 = 0.0f, a2 = 0.0f, a3 = 0.0f;
#pragma unroll 8
        for (int n = 0; n < M_TILE; n += 4) {
            a0 = fmaf(sw[n],     vb[(size_t)n * DD],       a0);
            a1 = fmaf(sw[n + 1], vb[(size_t)(n + 1) * DD], a1);
            a2 = fmaf(sw[n + 2], vb[(size_t)(n + 2) * DD], a2);
            a3 = fmaf(sw[n + 3], vb[(size_t)(n + 3) * DD], a3);
        }
        atomicAdd(&g_t[b * DD + tid], (a0 + a1) + (a2 + a3));
    }
}

// ---------------------------------------------------------------------------
// Kernel 3: out[b,k] += (t[b, oct]/Z[b]) @ Wi[oct, k]   (atomic partial)
// grid (B, 8): blockIdx.y = 64-wide d-octant. 256 threads = 64 k-quads x
// 4 d-subgroups of 16. One coalesced LDG.128 of Wi per step, 4 FMA chains.
// ---------------------------------------------------------------------------
__global__ __launch_bounds__(256)
void out_kernel(const float* __restrict__ Wi, float* __restrict__ out) {
    const int b   = blockIdx.x;
    const int oct = blockIdx.y;       // d range [oct*64, +64)
    const int tid = threadIdx.x;
    const int kq  = tid & 63;         // k = kq*4
    const int dg  = tid >> 6;         // 0..3 -> d-sub [oct*64 + dg*16, +16)

    __shared__ float st[64];
    __shared__ float4 sred[4][64];

    if (tid < 64) st[tid] = g_t[b * DD + oct * 64 + tid] * (1.0f / g_Z[b]);
    __syncthreads();

    const float4* w = (const float4*)(Wi + (size_t)oct * 64 * KK) + kq;
    float4 acc = make_float4(0.0f, 0.0f, 0.0f, 0.0f);
    const int d0 = dg * 16;
#pragma unroll
    for (int d = d0; d < d0 + 16; d++) {
        const float4 wv = w[(size_t)d * (KK / 4)];
        const float s = st[d];
        acc.x = fmaf(s, wv.x, acc.x);
        acc.y = fmaf(s, wv.y, acc.y);
        acc.z = fmaf(s, wv.z, acc.z);
        acc.w = fmaf(s, wv.w, acc.w);
    }
    sred[dg][kq] = acc;
    __syncthreads();

    if (tid < 64) {
        float4 a = sred[0][tid];
#pragma unroll
        for (int g = 1; g < 4; g++) {
            const float4 p = sred[g][tid];
            a.x += p.x; a.y += p.y; a.z += p.z; a.w += p.w;
        }
        float* o = out + b * KK + tid * 4;
        atomicAdd(o + 0, a.x);
        atomicAdd(o + 1, a.y);
        atomicAdd(o + 2, a.z);
        atomicAdd(o + 3, a.w);
    }
}

// ---------------------------------------------------------------------------
// Launch. Inputs: vI, vQ, Wi, Wq, bq, Wp, bp
// ---------------------------------------------------------------------------
extern "C" void kernel_launch(void* const* d_in, const int* in_sizes, int n_in,
                              void* d_out, int out_size) {
    const float* vI = (const float*)d_in[0];
    const float* vQ = (const float*)d_in[1];
    const float* Wi = (const float*)d_in[2];
    const float* Wq = (const float*)d_in[3];
    const float* bq = (const float*)d_in[4];
    const float* Wp = (const float*)d_in[5];
    // bp shifts scores uniformly -> softmax-invariant; unused.
    float* out = (float*)d_out;

    cudaFuncSetAttribute(scores_mma_kernel,
                         cudaFuncAttributeMaxDynamicSharedMemorySize, SCORES_SMEM);

    {
        dim3 grid(DD / 32, KK / 32);
        dim3 blk(32, 32);
        transpose_wi_kernel<<<grid, blk>>>(Wi);
    }
    {
        dim3 grid(BB, 8);
        vqp_kernel<<<grid, 256>>>(vQ, Wq, bq, out);
    }
    {
        dim3 grid(NN / M_TILE, BB);  // 16 x 32 = 512 CTAs
        scores_mma_kernel<<<grid, 512, SCORES_SMEM>>>(vI, Wp);
    }
    {
        dim3 grid(BB, 8);
        out_kernel<<<grid, 256>>>(Wi, out);
    }
}